// round 17
// baseline (speedup 1.0000x reference)
#include <cuda_runtime.h>
#include <cstdint>

// SpectralNetLoss: W [8192,8192] f32, Y [8192,32] f32 -> scalar f32.
// WY = W @ Y and d = W @ 1 in ONE tf32 GEMM (mma.sync m16n8k8, sm_80 baseline
// ISA — harness targets sm_103 without 'a'; no tcgen05/TMA).
// R13/R14 lesson: need fat warp tiles (m32, low B-duplication) AND high warp
// count. This round: MT=256, 8 warps x m32n40, 256 thr, XOR-swizzled A,
// ones-block B fragment synthesized in registers (not stored/loaded),
// KT=32, STAGES=3 -> 108KB smem, 2 CTAs/SM, 16 warps/SM.

#define MDIM    8192
#define KDIM    32
#define NB      40                  // 32 Y cols + 8 ones cols (row sums d)
#define MT      256                 // rows per row-block
#define KT      32                  // K per tile
#define NRB     (MDIM / MT)         // 32 row-blocks
#define NKT     (MDIM / KT)         // 256 k-tiles
#define KSPLIT  8
#define KRANGE  (MDIM / KSPLIT)     // 1024
#define TILES   (KRANGE / KT)       // 32 per CTA
#define STAGES  3
#define THREADS 256

#define A_TILE_F  (MT * KT)                  // 8192 floats (32KB, swizzled)
#define BFRAG_F   (KDIM * KT)                // 1024 floats per k-tile (ones skipped)
#define STAGE_F   (A_TILE_F + BFRAG_F)       // 9216 floats
#define STAGE_B   (STAGE_F * 4)              // 36864 B
#define DYN_SMEM  (STAGES * STAGE_B)         // 110592 B (2 CTAs/SM: 216KB)

// Scratch (no device allocs allowed).
__device__ float g_B[NKT * BFRAG_F];          // fragmented B' (Y part), 1 MB
__device__ float g_wy[MDIM * KDIM];           // final WY accumulator, 1 MB
__device__ float g_d[MDIM];                   // final row sums, 32 KB
__device__ int   g_cnt[NRB];                  // per-row-block completion count

__device__ __forceinline__ uint32_t smem_u32(const void* p) {
    return (uint32_t)__cvta_generic_to_shared(p);
}
__device__ __forceinline__ void cp_async16(uint32_t dst, const void* src) {
    asm volatile("cp.async.cg.shared.global [%0], [%1], 16;\n" :: "r"(dst), "l"(src));
}
#define CP_COMMIT() asm volatile("cp.async.commit_group;\n" ::: "memory")
#define CP_WAIT(n)  asm volatile("cp.async.wait_group %0;\n" :: "n"(n) : "memory")

__device__ __forceinline__ void mma_tf32(float* c, const uint32_t* a, uint32_t b0,
                                         uint32_t b1) {
    asm volatile(
        "mma.sync.aligned.m16n8k8.row.col.f32.tf32.tf32.f32 "
        "{%0,%1,%2,%3}, {%4,%5,%6,%7}, {%8,%9}, {%0,%1,%2,%3};"
        : "+f"(c[0]), "+f"(c[1]), "+f"(c[2]), "+f"(c[3])
        : "r"(a[0]), "r"(a[1]), "r"(a[2]), "r"(a[3]), "r"(b0), "r"(b1));
}

// A tile: row r stores 16B chunk ci at r*128 + (ci^(r&7))*16 (conflict-free).
__device__ __forceinline__ const float* a_addr(const float* base, int r, int k) {
    return base + r * 32 + (((k >> 2) ^ (r & 7)) << 2) + (k & 3);
}

// ---------------------------------------------------------------------------
// Prep: build fragmented B' (Y cols only; ones synthesized at compute time),
// zero g_wy / g_d / g_cnt / out.
// Fragment flat f (0..1023) -> (nt,ks2,g,tig,e):
//   f = (((nt*2+ks2)*8+g)*4+tig)*4+e,  n = nt*8+g (<32),
//   k_local = (2*ks2+(e>>1))*8 + tig + (e&1)*4,  value = Y[k][n].
// ---------------------------------------------------------------------------
__global__ void __launch_bounds__(256)
prep_kernel(const float* __restrict__ Y, float* __restrict__ out) {
    __shared__ float Ys[KT][KDIM + 1];
    const int t   = blockIdx.x;          // k-tile 0..255
    const int tid = threadIdx.x;

    {   // coalesced 32x32 Y tile load
        const float4* src = (const float4*)(Y + (size_t)t * KT * KDIM);
        float4 v = src[tid];
        int j = tid >> 3, c = (tid & 7) * 4;
        Ys[j][c] = v.x; Ys[j][c+1] = v.y; Ys[j][c+2] = v.z; Ys[j][c+3] = v.w;
    }
    __syncthreads();

    float* dst = g_B + (size_t)t * BFRAG_F;
    #pragma unroll
    for (int p = 0; p < BFRAG_F / 256; ++p) {        // 4 coalesced bursts
        int f   = tid + p * 256;
        int e   = f & 3;
        int tig = (f >> 2) & 3;
        int g   = (f >> 4) & 7;
        int ks2 = (f >> 7) & 1;
        int nt  = f >> 8;                            // 0..3 (Y cols only)
        int n   = nt * 8 + g;
        int kl  = (2 * ks2 + (e >> 1)) * 8 + tig + (e & 1) * 4;
        dst[f] = Ys[kl][n];
    }

    // zero accumulators: 256 blocks x 256 thr x 1 float4 == 262144 floats
    ((float4*)g_wy)[t * 256 + tid] = make_float4(0.f, 0.f, 0.f, 0.f);
    if (t < 32) g_d[t * 256 + tid] = 0.0f;
    if (t == 0 && tid < NRB) g_cnt[tid] = 0;
    if (t == 0 && tid == 0) out[0] = 0.0f;
}

// ---------------------------------------------------------------------------
// Main GEMM + fused loss. CTA (rb, ks): D[256 x 40] over its K range.
// 8 warps x m32n40. Atomic flush; last CTA per row-block computes loss part.
// ---------------------------------------------------------------------------
__global__ void __launch_bounds__(THREADS, 2)
mma_main(const float* __restrict__ W, const float* __restrict__ Y,
         float* __restrict__ out) {
    extern __shared__ float sm[];
    __shared__ int s_last;
    __shared__ float s_red[8];

    const int tid  = threadIdx.x;
    const int wid  = tid >> 5;           // 0..7 -> m-base wid*32
    const int lid  = tid & 31;
    const int g    = lid >> 2;
    const int tig  = lid & 3;
    const int rb   = blockIdx.x;
    const int row0 = rb * MT;
    const int kb0  = blockIdx.y * KRANGE;
    const int tg0  = kb0 / KT;

    const uint32_t sbase = smem_u32(sm);
    const uint32_t ONEB  = __float_as_uint(1.0f);

    float acc[2][5][4];                  // [m16 half][n-tile][frag]
    #pragma unroll
    for (int mh = 0; mh < 2; ++mh)
        #pragma unroll
        for (int nt = 0; nt < 5; ++nt)
            #pragma unroll
            for (int q = 0; q < 4; ++q) acc[mh][nt][q] = 0.0f;

    // ---- stage loader: W 256x32 swizzled + fragmented B (linear 4KB) ----
    auto load_tile = [&](int t) {
        const uint32_t sb   = sbase + (t % STAGES) * STAGE_B;
        const float*   wsrc = W + (size_t)row0 * MDIM + kb0 + t * KT;
        #pragma unroll
        for (int p = 0; p < 8; ++p) {                    // W: 2048 x 16B chunks
            int c = tid + p * 256;
            int r = c >> 3, ci = c & 7;
            cp_async16(sb + r * 128 + ((ci ^ (r & 7)) << 4),
                       wsrc + (size_t)r * MDIM + ci * 4);
        }
        const float* bsrc = g_B + (size_t)(tg0 + t) * BFRAG_F;
        cp_async16(sb + A_TILE_F * 4 + tid * 16, bsrc + tid * 4);
    };

    #pragma unroll
    for (int t = 0; t < STAGES - 1; ++t) { load_tile(t); CP_COMMIT(); }

    for (int t = 0; t < TILES; ++t) {
        if (t + STAGES - 1 < TILES) load_tile(t + STAGES - 1);
        CP_COMMIT();
        CP_WAIT(STAGES - 1);                 // tile t resident
        __syncthreads();

        const float* As = sm + (t % STAGES) * STAGE_F;
        const float* Bs = As + A_TILE_F;
        const int rloc = wid * 32 + g;       // rows rloc, +8, +16, +24

        #pragma unroll
        for (int ks2 = 0; ks2 < 2; ++ks2) {
            float4 b4[4];                    // Y-cols fragments (conflict-free)
            #pragma unroll
            for (int nt = 0; nt < 4; ++nt)
                b4[nt] = *(const float4*)&Bs[((nt * 2 + ks2) * 32 + lid) * 4];

            #pragma unroll
            for (int sub = 0; sub < 2; ++sub) {
                const int k0 = (ks2 * 2 + sub) * 8;
                uint32_t a0[4], a1[4];
                a0[0] = __float_as_uint(*a_addr(As, rloc,      k0 + tig));
                a0[1] = __float_as_uint(*a_addr(As, rloc + 8,  k0 + tig));
                a0[2] = __float_as_uint(*a_addr(As, rloc,      k0 + tig + 4));
                a0[3] = __float_as_uint(*a_addr(As, rloc + 8,  k0 + tig + 4));
                a1[0] = __float_as_uint(*a_addr(As, rloc + 16, k0 + tig));
                a1[1] = __float_as_uint(*a_addr(As, rloc + 24, k0 + tig));
                a1[2] = __float_as_uint(*a_addr(As, rloc + 16, k0 + tig + 4));
                a1[3] = __float_as_uint(*a_addr(As, rloc + 24, k0 + tig + 4));
                #pragma unroll
                for (int nt = 0; nt < 4; ++nt) {
                    uint32_t b0 = __float_as_uint(sub ? b4[nt].z : b4[nt].x);
                    uint32_t b1 = __float_as_uint(sub ? b4[nt].w : b4[nt].y);
                    mma_tf32(acc[0][nt], a0, b0, b1);
                    mma_tf32(acc[1][nt], a1, b0, b1);
                }
                mma_tf32(acc[0][4], a0, ONEB, ONEB);   // ones block -> row sums
                mma_tf32(acc[1][4], a1, ONEB, ONEB);
            }
        }
        __syncthreads();
    }

    // ---- flush: atomic accumulate into final g_wy / g_d ----
    #pragma unroll
    for (int mh = 0; mh < 2; ++mh) {
        const int rA = row0 + wid * 32 + mh * 16 + g;
        const int rB = rA + 8;
        #pragma unroll
        for (int nt = 0; nt < 4; ++nt) {
            int col = nt * 8 + 2 * tig;
            atomicAdd(&g_wy[(size_t)rA * KDIM + col],     acc[mh][nt][0]);
            atomicAdd(&g_wy[(size_t)rA * KDIM + col + 1], acc[mh][nt][1]);
            atomicAdd(&g_wy[(size_t)rB * KDIM + col],     acc[mh][nt][2]);
            atomicAdd(&g_wy[(size_t)rB * KDIM + col + 1], acc[mh][nt][3]);
        }
        if (tig == 0) {
            atomicAdd(&g_d[rA], acc[mh][4][0]);
            atomicAdd(&g_d[rB], acc[mh][4][2]);
        }
    }

    // ---- fused loss: last CTA of this row-block computes its contribution ----
    __threadfence();
    __syncthreads();
    if (tid == 0) s_last = (atomicAdd(&g_cnt[rb], 1) == KSPLIT - 1);
    __syncthreads();
    if (s_last) {
        __threadfence();                     // acquire side
        const int row = row0 + tid;          // 256 threads, one row each
        float dinv = 1.0f / __ldcg(&g_d[row]);
        float s = 0.0f;
        #pragma unroll
        for (int k = 0; k < KDIM; ++k) {
            float y = Y[(size_t)row * KDIM + k];
            s += y * (y - __ldcg(&g_wy[(size_t)row * KDIM + k]) * dinv);
        }
        #pragma unroll
        for (int o = 16; o; o >>= 1) s += __shfl_xor_sync(0xffffffffu, s, o);
        if (lid == 0) s_red[wid] = s;
    }
    __syncthreads();
    if (s_last && tid == 0) {
        float tot = 0.0f;
        #pragma unroll
        for (int wq = 0; wq < 8; ++wq) tot += s_red[wq];
        atomicAdd(out, tot * (1.0f / (float)MDIM));
    }
}

// ---------------------------------------------------------------------------
extern "C" void kernel_launch(void* const* d_in, const int* in_sizes, int n_in,
                              void* d_out, int out_size) {
    const float* W = (const float*)d_in[0];
    const float* Y = (const float*)d_in[1];
    float* out = (float*)d_out;

    cudaFuncSetAttribute(mma_main, cudaFuncAttributeMaxDynamicSharedMemorySize,
                         DYN_SMEM);

    prep_kernel<<<NKT, 256>>>(Y, out);               // 256 blocks

    dim3 grid(NRB, KSPLIT);                          // (32, 8) = 256 CTAs
    mma_main<<<grid, THREADS, DYN_SMEM>>>(W, Y, out);
}